// round 4
// baseline (speedup 1.0000x reference)
#include <cuda_runtime.h>

#define DATA_DIM 512
#define BASIS_DIM 64
#define N_ROWS 2048
#define N_SPANS 61          // interior knot intervals
#define THREADS 128         // main kernel: one float4 of x per thread

// Combined per-(dim, span) cubic coefficients: contribution of dim i on span m
// is C0 + C1*u + C2*u^2 + C3*u^3, u = 61*x - m.  512*61*16B = ~500 KB.
__device__ float4 g_C[DATA_DIM * N_SPANS];

// ---------------- init: build coefficient table (runs every call) ----------------

// Clamped open-uniform knots: t[g] = clamp(g-3, 0, 61) / 61
__device__ __forceinline__ float knotf(int g) {
    int j = g - 3;
    j = max(0, min(N_SPANS, j));
    return (float)j / (float)N_SPANS;
}

// de Boor weights of the 4 nonzero cubic basis funcs, span m fixed, exact divides.
__device__ float4 deboor_weights(float xx, int m) {
    int k = m + 3;
    float left1  = xx - knotf(k);
    float left2  = xx - knotf(k - 1);
    float left3  = xx - knotf(k - 2);
    float right1 = knotf(k + 1) - xx;
    float right2 = knotf(k + 2) - xx;
    float right3 = knotf(k + 3) - xx;

    float N0 = 1.0f, N1, N2, N3, saved, temp;
    temp = N0 / (right1 + left1);
    N0 = right1 * temp;  N1 = left1 * temp;
    temp = N0 / (right1 + left2);
    N0 = right1 * temp;  saved = left2 * temp;
    temp = N1 / (right2 + left1);
    N1 = saved + right2 * temp;  N2 = left1 * temp;
    temp = N0 / (right1 + left3);
    N0 = right1 * temp;  saved = left3 * temp;
    temp = N1 / (right2 + left2);
    N1 = saved + right2 * temp;  saved = left2 * temp;
    temp = N2 / (right3 + left1);
    N2 = saved + right3 * temp;  N3 = left1 * temp;
    return make_float4(N0, N1, N2, N3);
}

__global__ void init_coeff_kernel(const float* __restrict__ A) {
    int idx = blockIdx.x * blockDim.x + threadIdx.x;
    if (idx >= DATA_DIM * N_SPANS) return;
    int i = idx / N_SPANS;
    int m = idx % N_SPANS;

    float a0 = A[i * BASIS_DIM + m + 0];
    float a1 = A[i * BASIS_DIM + m + 1];
    float a2 = A[i * BASIS_DIM + m + 2];
    float a3 = A[i * BASIS_DIM + m + 3];

    // Sample the (exact cubic) contribution at u = 0, 1/3, 2/3, 1 on span m.
    float f[4];
    #pragma unroll
    for (int s = 0; s < 4; s++) {
        float xs = (float)(3 * m + s) / (3.0f * (float)N_SPANS);  // x = (m + s/3)/61
        float4 w = deboor_weights(xs, m);
        f[s] = w.x * a0 + w.y * a1 + w.z * a2 + w.w * a3;
    }

    // Exact inverse Vandermonde for nodes {0, 1/3, 2/3, 1} -> monomial coeffs in u.
    float c0 = f[0];
    float c1 = -5.5f * f[0] +  9.0f * f[1] -  4.5f * f[2] +        f[3];
    float c2 =  9.0f * f[0] - 22.5f * f[1] + 18.0f * f[2] - 4.5f * f[3];
    float c3 = -4.5f * f[0] + 13.5f * f[1] - 13.5f * f[2] + 4.5f * f[3];

    g_C[idx] = make_float4(c0, c1, c2, c3);
}

// ---------------- main: per-row cubic Horner + reduce ----------------

__global__ void __launch_bounds__(THREADS)
bspline_eval_kernel(const float* __restrict__ x, float* __restrict__ out) {
    const int row = blockIdx.x;
    const int tid = threadIdx.x;
    const int i0 = tid * 4;

    const float4 xv = reinterpret_cast<const float4*>(x + (size_t)row * DATA_DIM)[tid];

    // span + fractional coordinate per component
    float t0 = xv.x * (float)N_SPANS, t1 = xv.y * (float)N_SPANS,
          t2 = xv.z * (float)N_SPANS, t3 = xv.w * (float)N_SPANS;
    int m0 = max(0, min(N_SPANS - 1, (int)t0));
    int m1 = max(0, min(N_SPANS - 1, (int)t1));
    int m2 = max(0, min(N_SPANS - 1, (int)t2));
    int m3 = max(0, min(N_SPANS - 1, (int)t3));
    float u0 = t0 - (float)m0, u1 = t1 - (float)m1,
          u2 = t2 - (float)m2, u3 = t3 - (float)m3;

    // issue all 4 coefficient loads up front (LDG.128, L2-resident table)
    float4 c0 = __ldg(&g_C[(i0 + 0) * N_SPANS + m0]);
    float4 c1 = __ldg(&g_C[(i0 + 1) * N_SPANS + m1]);
    float4 c2 = __ldg(&g_C[(i0 + 2) * N_SPANS + m2]);
    float4 c3 = __ldg(&g_C[(i0 + 3) * N_SPANS + m3]);

    float sum = fmaf(fmaf(fmaf(c0.w, u0, c0.z), u0, c0.y), u0, c0.x)
              + fmaf(fmaf(fmaf(c1.w, u1, c1.z), u1, c1.y), u1, c1.x)
              + fmaf(fmaf(fmaf(c2.w, u2, c2.z), u2, c2.y), u2, c2.x)
              + fmaf(fmaf(fmaf(c3.w, u3, c3.z), u3, c3.y), u3, c3.x);

    #pragma unroll
    for (int o = 16; o > 0; o >>= 1)
        sum += __shfl_xor_sync(0xFFFFFFFFu, sum, o);

    __shared__ float ws[THREADS / 32];
    if ((tid & 31) == 0) ws[tid >> 5] = sum;
    __syncthreads();

    if (tid == 0) {
        float s = ws[0] + ws[1] + ws[2] + ws[3];
        out[row] = 1.0f / (1.0f + __expf(-s));
    }
}

extern "C" void kernel_launch(void* const* d_in, const int* in_sizes, int n_in,
                              void* d_out, int out_size) {
    // Disambiguate by element count: x is 2048*512, A is 512*64.
    const float* x = (const float*)d_in[0];
    const float* A = (const float*)d_in[1];
    if (n_in >= 2 && in_sizes[0] == DATA_DIM * BASIS_DIM &&
        in_sizes[1] == N_ROWS * DATA_DIM) {
        x = (const float*)d_in[1];
        A = (const float*)d_in[0];
    }
    float* out = (float*)d_out;  // [2048]

    const int init_items = DATA_DIM * N_SPANS;
    init_coeff_kernel<<<(init_items + 255) / 256, 256>>>(A);
    bspline_eval_kernel<<<N_ROWS, THREADS>>>(x, out);
}